// round 17
// baseline (speedup 1.0000x reference)
#include <cuda_runtime.h>
#include <cstdint>

#define B        2
#define N_PRE    50000
#define N_POST   50000
#define N_SYN    10000000
#define N_TYPES  20
#define N_BASIS  5

#define MASK_WORDS (N_PRE / 16)          // 3125 words (2 bits/neuron)
#define N_ROWS     (B * N_POST)          // 100000

__device__ uint32_t g_spike_mask[MASK_WORDS];
// COLUMN-MAJOR per-type weight sums: g_S[t * N_ROWS + row], row = b*N_POST+post.
// Zero at module load; compact_kernel re-zeroes after reading, so it is zero
// at entry of EVERY kernel_launch call.
__device__ __align__(16) float g_S[N_TYPES * N_ROWS];   // 8 MB

// ---------------------------------------------------------------------------
// prep: ballot-based packed 2-bit spike mask. Launched with the PDL attribute:
// across graph replays it overlaps the PREVIOUS replay's compact (no hazard —
// prep writes only g_spike_mask, whose last reader accum(i) finished before
// compact(i) began).
__global__ void prep_kernel(const float* __restrict__ spikes)
{
    int tid = blockIdx.x * blockDim.x + threadIdx.x;
    if (tid >= ((N_PRE + 31) & ~31)) return;
    int n = tid;
    bool f0 = false, f1 = false;
    if (n < N_PRE) {
        f0 = (__ldg(spikes + n) != 0.0f);
        f1 = (__ldg(spikes + N_PRE + n) != 0.0f);
    }
    uint32_t b0 = __ballot_sync(0xFFFFFFFFu, f0);
    uint32_t b1 = __ballot_sync(0xFFFFFFFFu, f1);
    int lane = threadIdx.x & 31;
    if (lane == 0 || lane == 16) {
        uint32_t h0 = (b0 >> lane) & 0xFFFFu;
        uint32_t h1 = (b1 >> lane) & 0xFFFFu;
        uint32_t m = 0;
        #pragma unroll
        for (int j = 0; j < 16; j++)
            m |= (((h0 >> j) & 1u) | (((h1 >> j) & 1u) << 1)) << (2 * j);
        int w = (n >> 4);
        if (w < MASK_WORDS) g_spike_mask[w] = m;
    }
}

// ---------------------------------------------------------------------------
__global__ __launch_bounds__(256)
void accum_kernel(const float* __restrict__ weights,       // [N_SYN]
                  const int4*  __restrict__ syn_idx4,      // [N_SYN/2]
                  const int4*  __restrict__ syn_ids4)      // [N_SYN/4]
{
    __shared__ uint32_t smask[MASK_WORDS];

    const int NG = N_SYN / 4;
    const int stride = gridDim.x * blockDim.x;
    const int g0 = blockIdx.x * blockDim.x + threadIdx.x;

    // Warm L2 with this thread's first index line while prep is running.
    if (g0 < NG) {
        const char* p = (const char*)(syn_idx4 + g0 * 2);
        asm volatile("prefetch.global.L2 [%0];" :: "l"(p));
    }

    cudaGridDependencySynchronize();   // wait for prep (PDL)

    for (int i = threadIdx.x; i < MASK_WORDS; i += blockDim.x)
        smask[i] = g_spike_mask[i];
    __syncthreads();

    for (int g = g0; g < NG; g += stride) {
        int4 u = __ldcs(syn_idx4 + g * 2);     // syn 4g+0:(u.x,u.y) 4g+1:(u.z,u.w)
        int4 v = __ldcs(syn_idx4 + g * 2 + 1); // syn 4g+2:(v.x,v.y) 4g+3:(v.z,v.w)

        uint32_t m0 = (smask[u.y >> 4] >> ((u.y & 15) << 1)) & 3u;
        uint32_t m1 = (smask[u.w >> 4] >> ((u.w & 15) << 1)) & 3u;
        uint32_t m2 = (smask[v.y >> 4] >> ((v.y & 15) << 1)) & 3u;
        uint32_t m3 = (smask[v.w >> 4] >> ((v.w & 15) << 1)) & 3u;

        if ((m0 | m1 | m2 | m3) == 0u) continue;   // ~85% of lanes skip

        // Streaming gathers: one-touch lines, keep g_S resident in L2.
        float4 wv = __ldcs((const float4*)(weights + g * 4));
        int4   tt = __ldcs(syn_ids4 + g);

        // Column-major scratch: addr = t * N_ROWS + (b*N_POST + post).
        float* r0 = g_S + (size_t)tt.x * N_ROWS + u.x;
        float* r1 = g_S + (size_t)tt.y * N_ROWS + u.z;
        float* r2 = g_S + (size_t)tt.z * N_ROWS + v.x;
        float* r3 = g_S + (size_t)tt.w * N_ROWS + v.z;

        if (m0 & 1u) atomicAdd(r0,          wv.x);
        if (m0 & 2u) atomicAdd(r0 + N_POST, wv.x);
        if (m1 & 1u) atomicAdd(r1,          wv.y);
        if (m1 & 2u) atomicAdd(r1 + N_POST, wv.y);
        if (m2 & 1u) atomicAdd(r2,          wv.z);
        if (m2 & 2u) atomicAdd(r2 + N_POST, wv.z);
        if (m3 & 1u) atomicAdd(r3,          wv.w);
        if (m3 & 2u) atomicAdd(r3 + N_POST, wv.w);
    }
}

// ---------------------------------------------------------------------------
// compact: one thread per row, column-major reads (coalesced, 20-way MLP),
// then owner-thread re-zero. Triggers programmatic launch completion early so
// the NEXT replay's prep can start while compact finishes.
__global__ __launch_bounds__(256)
void compact_kernel(const float* __restrict__ basis, float* __restrict__ out)
{
    __shared__ float sb[N_TYPES * N_BASIS];

    int tid = threadIdx.x;
    if (tid < N_TYPES * N_BASIS) sb[tid] = basis[tid];
    __syncthreads();

    cudaGridDependencySynchronize();   // wait for accum before touching g_S

    // Allow the dependent kernel (next replay's prep) to launch now.
    cudaTriggerProgrammaticLaunchCompletion();

    int row = blockIdx.x * 256 + tid;
    if (row >= N_ROWS) return;

    float s[N_TYPES];
    #pragma unroll
    for (int t = 0; t < N_TYPES; t++)
        s[t] = g_S[(size_t)t * N_ROWS + row];   // coalesced, 20-way MLP

    float acc[N_BASIS];
    #pragma unroll
    for (int r = 0; r < N_BASIS; r++) acc[r] = 0.f;
    #pragma unroll
    for (int t = 0; t < N_TYPES; t++) {
        #pragma unroll
        for (int r = 0; r < N_BASIS; r++)
            acc[r] += s[t] * sb[t * N_BASIS + r];
    }

    float* o = out + (size_t)row * N_BASIS;
    o[0] = acc[0]; o[1] = acc[1]; o[2] = acc[2]; o[3] = acc[3]; o[4] = acc[4];

    // Re-zero this row's column entries for the next call (coalesced).
    #pragma unroll
    for (int t = 0; t < N_TYPES; t++)
        g_S[(size_t)t * N_ROWS + row] = 0.f;
}

extern "C" void kernel_launch(void* const* d_in, const int* in_sizes, int n_in,
                              void* d_out, int out_size)
{
    const float* spikes  = (const float*)d_in[0];
    const float* weights = (const float*)d_in[1];
    const float* basis   = (const float*)d_in[2];
    const int4*  syn_idx = (const int4*)d_in[3];
    const int4*  syn_ids = (const int4*)d_in[4];
    float* out = (float*)d_out;

    // prep: PDL secondary — across graph replays it may overlap the previous
    // replay's compact (which triggers early). Within a replay it still
    // strictly precedes accum (accum gridDepSyncs on it).
    {
        cudaLaunchAttribute attr[1];
        attr[0].id = cudaLaunchAttributeProgrammaticStreamSerialization;
        attr[0].val.programmaticStreamSerializationAllowed = 1;
        cudaLaunchConfig_t cfg = {};
        cfg.gridDim  = dim3(196, 1, 1);
        cfg.blockDim = dim3(256, 1, 1);
        cfg.stream = 0;
        cfg.attrs = attr;
        cfg.numAttrs = 1;
        cudaLaunchKernelEx(&cfg, prep_kernel, spikes);
    }

    {
        cudaLaunchAttribute attr[1];
        attr[0].id = cudaLaunchAttributeProgrammaticStreamSerialization;
        attr[0].val.programmaticStreamSerializationAllowed = 1;
        cudaLaunchConfig_t cfg = {};
        cfg.gridDim  = dim3(1184, 1, 1);
        cfg.blockDim = dim3(256, 1, 1);
        cfg.stream = 0;
        cfg.attrs = attr;
        cfg.numAttrs = 1;
        cudaLaunchKernelEx(&cfg, accum_kernel, weights, syn_idx, syn_ids);
    }

    {
        cudaLaunchAttribute attr[1];
        attr[0].id = cudaLaunchAttributeProgrammaticStreamSerialization;
        attr[0].val.programmaticStreamSerializationAllowed = 1;
        cudaLaunchConfig_t cfg = {};
        cfg.gridDim  = dim3((N_ROWS + 255) / 256, 1, 1);   // 391 blocks
        cfg.blockDim = dim3(256, 1, 1);
        cfg.stream = 0;
        cfg.attrs = attr;
        cfg.numAttrs = 1;
        cudaLaunchKernelEx(&cfg, compact_kernel, basis, out);
    }
}